// round 7
// baseline (speedup 1.0000x reference)
#include <cuda_runtime.h>

#define P_RAYS 262144
#define FULLM 0xFFFFFFFFu
#define R1GRID 256

__device__ float g_part0[R1GRID];
__device__ float g_part1[R1GRID];
__device__ int   g_cntp[R1GRID];
__device__ float g_mean0;
__device__ float g_mean1;

// Pass 1: 256 blocks x 256 threads; block stages 1024 rays (768 float4) thru smem.
__global__ void __launch_bounds__(256) k_reduce1(const float* __restrict__ rd,
                                                 const float* __restrict__ cam) {
    __shared__ float4 st4[768];                 // 12KB
    __shared__ float  w0s[8], w1s[8];
    __shared__ int    wcs[8];
    const int tid = threadIdx.x;
    const float4* rd4 = reinterpret_cast<const float4*>(rd);
    const int base4 = blockIdx.x * 768;
    st4[tid]       = rd4[base4 + tid];
    st4[tid + 256] = rd4[base4 + tid + 256];
    st4[tid + 512] = rd4[base4 + tid + 512];
    __syncthreads();

    const float cx = cam[0], cy = cam[1], cz = cam[2];
    const float cc = cx * cx + cy * cy + cz * cz;
    const float* sf = reinterpret_cast<const float*>(st4);

    float a0 = 0.f, a1 = 0.f; int cnt = 0;
    #pragma unroll
    for (int k = 0; k < 4; k++) {
        int ray = tid + 256 * k;                // local ray in [0,1024)
        const float dx = sf[3 * ray + 0];
        const float dy = sf[3 * ray + 1];
        const float dz = sf[3 * ray + 2];
        float dot = dx * cx + dy * cy + dz * cz;
        float under = dot * dot - (cc - 1.0f);
        if (under > 0.0f) {
            float sq = sqrtf(under);
            a0 += (-sq - dot);
            a1 += ( sq - dot);
            cnt++;
        }
    }
    // warp reduce
    #pragma unroll
    for (int off = 16; off > 0; off >>= 1) {
        a0  += __shfl_down_sync(FULLM, a0, off);
        a1  += __shfl_down_sync(FULLM, a1, off);
        cnt += __shfl_down_sync(FULLM, cnt, off);
    }
    const int wid = tid >> 5, lane = tid & 31;
    if (lane == 0) { w0s[wid] = a0; w1s[wid] = a1; wcs[wid] = cnt; }
    __syncthreads();
    if (wid == 0) {
        float b0 = (lane < 8) ? w0s[lane] : 0.f;
        float b1 = (lane < 8) ? w1s[lane] : 0.f;
        int   bc = (lane < 8) ? wcs[lane] : 0;
        #pragma unroll
        for (int off = 4; off > 0; off >>= 1) {
            b0 += __shfl_down_sync(FULLM, b0, off);
            b1 += __shfl_down_sync(FULLM, b1, off);
            bc += __shfl_down_sync(FULLM, bc, off);
        }
        if (lane == 0) { g_part0[blockIdx.x] = b0; g_part1[blockIdx.x] = b1; g_cntp[blockIdx.x] = bc; }
    }
}

// Pass 2: final reduce over 256 partials
__global__ void __launch_bounds__(256) k_reduce2() {
    __shared__ float s0[R1GRID], s1[R1GRID];
    __shared__ int   sc[R1GRID];
    const int tid = threadIdx.x;
    s0[tid] = g_part0[tid]; s1[tid] = g_part1[tid]; sc[tid] = g_cntp[tid];
    __syncthreads();
    for (int s = R1GRID / 2; s > 0; s >>= 1) {
        if (tid < s) { s0[tid] += s0[tid + s]; s1[tid] += s1[tid + s]; sc[tid] += sc[tid + s]; }
        __syncthreads();
    }
    if (tid == 0) {
        float n = (float)(sc[0] > 1 ? sc[0] : 1);
        g_mean0 = s0[0] / n;
        g_mean1 = s1[0] / n;
    }
}

// Main kernel: ONE WARP PER RAY. Lane l holds steps (2l, 2l+1). No shared memory.
__global__ void __launch_bounds__(256) k_main(const float* __restrict__ rd,
                                              const float* __restrict__ cam,
                                              const float* __restrict__ trand,
                                              float* __restrict__ out) {
    const int lane = threadIdx.x & 31;
    const int r = (blockIdx.x * blockDim.x + threadIdx.x) >> 5;  // ray = global warp id

    const float cx = cam[0], cy = cam[1], cz = cam[2];
    const float cc = cx * cx + cy * cy + cz * cz;

    const float dx = __ldg(rd + 3 * r + 0);
    const float dy = __ldg(rd + 3 * r + 1);
    const float dz = __ldg(rd + 3 * r + 2);
    const float dot = dx * cx + dy * cy + dz * cz;
    const float under = dot * dot - (cc - 1.0f);

    float si0, si1;
    if (under > 0.0f) {
        float sq = sqrtf(under);
        si0 = -sq - dot;
        si1 =  sq - dot;
    } else {
        si0 = g_mean0;
        si1 = g_mean1;
    }
    const float min_d = fmaxf(si0, 0.0f);
    const float max_d = fmaxf(si1, 0.0f);
    const float range = max_d - min_d;
    const float sd = range * (1.0f / 64.0f);

    // ---- per-lane pair of steps ----
    const float2 t2 = reinterpret_cast<const float2*>(trand)[(size_t)r * 32 + lane];
    const int j0 = 2 * lane, j1 = 2 * lane + 1;

    // b = exp(-inv_s * (sqrt(q)-0.5)) = exp2( K*sqrt(q) - K/2 ),  K = -inv_s*log2(e)
    const float K  = -28.97759184f;             // -e^3 * 1.4426950409
    const float Kh = 14.48879592f;              // -K/2

    float step0 = fmaf((float)j0 * (1.0f / 63.0f), range, min_d) + (t2.x - 0.5f) * sd;
    float step1 = fmaf((float)j1 * (1.0f / 63.0f), range, min_d) + (t2.y - 0.5f) * sd;

    float q0 = fmaxf(fmaf(step0, step0 + 2.0f * dot, cc), 1e-12f);
    float q1 = fmaxf(fmaf(step1, step1 + 2.0f * dot, cc), 1e-12f);
    float sq0 = q0 * rsqrtf(q0);
    float sq1 = q1 * rsqrtf(q1);
    float b0 = exp2f(fmaf(sq0, K, Kh));
    float b1 = exp2f(fmaf(sq1, K, Kh));
    float sig0 = __fdividef(1.0f, 1.0f + b0);
    float sig1 = __fdividef(1.0f, 1.0f + b1);

    float signext = __shfl_down_sync(FULLM, sig0, 1);

    // 1/(sig + 1e-8) approx: (1+b)*(1 - 1e-8*(1+b))
    float ib0 = 1.0f + b0;
    float ib1 = 1.0f + b1;
    float invse0 = ib0 * (1.0f - 1e-8f * ib0);
    float invse1 = ib1 * (1.0f - 1e-8f * ib1);

    float alpha0 = (sig0 - sig1 + 1e-8f) * invse0;
    float alpha1 = (sig1 - signext + 1e-8f) * invse1;
    alpha0 = fminf(fmaxf(alpha0, 0.0f), 1.0f);
    alpha1 = fminf(fmaxf(alpha1, 0.0f), 1.0f);
    if (lane == 31) alpha1 = 0.0f;

    // ---- transmittance: exclusive product scan ----
    float g0v = 1.0f - alpha0 + 1e-7f;
    float g1v = 1.0f - alpha1 + 1e-7f;
    float incl = g0v * g1v;
    #pragma unroll
    for (int off = 1; off < 32; off <<= 1) {
        float v = __shfl_up_sync(FULLM, incl, off);
        if (lane >= off) incl *= v;
    }
    float excl = __shfl_up_sync(FULLM, incl, 1);
    if (lane == 0) excl = 1.0f;
    float trans0 = excl;
    float trans1 = excl * g0v;

    float w0 = alpha0 * trans0;
    float w1 = alpha1 * trans1;

    // ---- unnormalized CDF: inclusive sum scan ----
    float e0 = w0 + 1e-8f;
    float e1 = w1 + 1e-8f;
    float sinc = e0 + e1;
    #pragma unroll
    for (int off = 1; off < 32; off <<= 1) {
        float v = __shfl_up_sync(FULLM, sinc, off);
        if (lane >= off) sinc += v;
    }
    float sexcl = __shfl_up_sync(FULLM, sinc, 1);
    if (lane == 0) sexcl = 0.0f;
    float c0 = sexcl + e0;        // C[2l]
    float c1 = c0 + e1;           // C[2l+1]

    const float wsum = __shfl_sync(FULLM, c0, 31);   // C[62]
    const float invW = __fdividef(1.0f, wsum);

    // ---- importance sampling: one sample per lane ----
    const float target = (float)(2 * lane + 1) * (1.0f / 64.0f) * wsum;

    int p = 0;
    #pragma unroll
    for (int s = 32; s > 0; s >>= 1) {
        int m = p + s - 1;
        float va = __shfl_sync(FULLM, c0, m >> 1);
        float vb = __shfl_sync(FULLM, c1, m >> 1);
        float v = (m & 1) ? vb : va;
        if (v <= target) p += s;
    }
    if (p > 62) p = 62;

    int mb = (p == 0) ? 0 : (p - 1);
    float cba = __shfl_sync(FULLM, c0, mb >> 1);
    float cbb = __shfl_sync(FULLM, c1, mb >> 1);
    float cdf_b = (p == 0) ? 0.0f : ((mb & 1) ? cbb : cba);

    float caa = __shfl_sync(FULLM, c0, p >> 1);
    float cab = __shfl_sync(FULLM, c1, p >> 1);
    float cdf_a = (p & 1) ? cab : caa;

    float sba = __shfl_sync(FULLM, step0, p >> 1);
    float sbb = __shfl_sync(FULLM, step1, p >> 1);
    float bins_b = (p & 1) ? sbb : sba;

    int pa = p + 1;
    float saa = __shfl_sync(FULLM, step0, pa >> 1);
    float sab = __shfl_sync(FULLM, step1, pa >> 1);
    float bins_a = (pa & 1) ? sab : saa;

    float dN = cdf_a - cdf_b;
    float tt = (target - cdf_b) * ((dN < 1e-8f * wsum) ? invW : __fdividef(1.0f, dN));
    float z = fmaf(tt, bins_a - bins_b, bins_b);

    // ---- z: fully coalesced ----
    float* zout = out + (size_t)P_RAYS * 96 + (size_t)r * 32;
    zout[lane] = z;

    // ---- new_samples: shuffle-packed float4 stores (lanes 0..23) ----
    {
        const int m = lane;
        const int q = m / 3;           // compile-time cheap (m<32)
        const int t = m - 3 * q;
        int a = 4 * q + ((t == 0) ? 0 : (t == 1) ? 1 : 2);
        int bsrc = a + 1;
        float za = __shfl_sync(FULLM, z, a & 31);
        float zb = __shfl_sync(FULLM, z, bsrc & 31);
        if (m < 24) {
            float4 v;
            if (t == 0) {          // c=(0,1,2,0) src=(a,a,a,b)
                v.x = fmaf(za, dx, cx);
                v.y = fmaf(za, dy, cy);
                v.z = fmaf(za, dz, cz);
                v.w = fmaf(zb, dx, cx);
            } else if (t == 1) {   // c=(1,2,0,1) src=(a,a,b,b)
                v.x = fmaf(za, dy, cy);
                v.y = fmaf(za, dz, cz);
                v.z = fmaf(zb, dx, cx);
                v.w = fmaf(zb, dy, cy);
            } else {               // c=(2,0,1,2) src=(a,b,b,b)
                v.x = fmaf(za, dz, cz);
                v.y = fmaf(zb, dx, cx);
                v.z = fmaf(zb, dy, cy);
                v.w = fmaf(zb, dz, cz);
            }
            reinterpret_cast<float4*>(out + (size_t)r * 96)[m] = v;
        }
    }

    // ---- weights: vectorized, parity-dependent alignment (row stride 63 floats) ----
    float* wout = out + (size_t)P_RAYS * 128 + (size_t)r * 63;
    float wnext = __shfl_down_sync(FULLM, w0, 1);   // w0 of lane+1 (= w[2l+2])
    if ((r & 1) == 0) {
        // row base 8B-aligned: pairs (2l,2l+1) for l<31, scalar w[62] on lane 31
        if (lane < 31) {
            *reinterpret_cast<float2*>(wout + j0) = make_float2(w0, w1);
        } else {
            wout[62] = w0;
        }
    } else {
        // row base 4B-odd: scalar w[0] on lane 0, pairs (2l+1,2l+2) for l<31
        if (lane == 0) wout[0] = w0;
        if (lane < 31) {
            *reinterpret_cast<float2*>(wout + j0 + 1) = make_float2(w1, wnext);
        }
    }
}

extern "C" void kernel_launch(void* const* d_in, const int* in_sizes, int n_in,
                              void* d_out, int out_size) {
    const float* rd  = (const float*)d_in[0];
    const float* cam = (const float*)d_in[1];
    const float* tr  = (const float*)d_in[2];
    float* out = (float*)d_out;

    k_reduce1<<<R1GRID, 256>>>(rd, cam);
    k_reduce2<<<1, R1GRID>>>();
    k_main<<<(P_RAYS * 32) / 256, 256>>>(rd, cam, tr, out);
}

// round 9
// speedup vs baseline: 1.2656x; 1.2656x over previous
#include <cuda_runtime.h>

#define P_RAYS 262144
#define FULLM 0xFFFFFFFFu
#define R1GRID 512

__device__ float g_part0[R1GRID];
__device__ float g_part1[R1GRID];
__device__ int   g_cntp[R1GRID];
__device__ float g_mean0;
__device__ float g_mean1;

// Pass 1: 512 blocks x 256 threads; block stages 512 rays (384 float4) thru smem.
__global__ void __launch_bounds__(256) k_reduce1(const float* __restrict__ rd,
                                                 const float* __restrict__ cam) {
    __shared__ float4 st4[384];                 // 6KB
    __shared__ float  w0s[8], w1s[8];
    __shared__ int    wcs[8];
    const int tid = threadIdx.x;
    const float4* rd4 = reinterpret_cast<const float4*>(rd);
    const int base4 = blockIdx.x * 384;
    st4[tid] = rd4[base4 + tid];
    if (tid < 128) st4[tid + 256] = rd4[base4 + tid + 256];
    __syncthreads();

    const float cx = cam[0], cy = cam[1], cz = cam[2];
    const float cc = cx * cx + cy * cy + cz * cz;
    const float* sf = reinterpret_cast<const float*>(st4);

    float a0 = 0.f, a1 = 0.f; int cnt = 0;
    #pragma unroll
    for (int k = 0; k < 2; k++) {
        int ray = tid + 256 * k;                // local ray in [0,512)
        const float dx = sf[3 * ray + 0];
        const float dy = sf[3 * ray + 1];
        const float dz = sf[3 * ray + 2];
        float dot = dx * cx + dy * cy + dz * cz;
        float under = dot * dot - (cc - 1.0f);
        if (under > 0.0f) {
            float sq = sqrtf(under);
            a0 += (-sq - dot);
            a1 += ( sq - dot);
            cnt++;
        }
    }
    #pragma unroll
    for (int off = 16; off > 0; off >>= 1) {
        a0  += __shfl_down_sync(FULLM, a0, off);
        a1  += __shfl_down_sync(FULLM, a1, off);
        cnt += __shfl_down_sync(FULLM, cnt, off);
    }
    const int wid = tid >> 5, lane = tid & 31;
    if (lane == 0) { w0s[wid] = a0; w1s[wid] = a1; wcs[wid] = cnt; }
    __syncthreads();
    if (wid == 0) {
        float b0 = (lane < 8) ? w0s[lane] : 0.f;
        float b1 = (lane < 8) ? w1s[lane] : 0.f;
        int   bc = (lane < 8) ? wcs[lane] : 0;
        #pragma unroll
        for (int off = 4; off > 0; off >>= 1) {
            b0 += __shfl_down_sync(FULLM, b0, off);
            b1 += __shfl_down_sync(FULLM, b1, off);
            bc += __shfl_down_sync(FULLM, bc, off);
        }
        if (lane == 0) { g_part0[blockIdx.x] = b0; g_part1[blockIdx.x] = b1; g_cntp[blockIdx.x] = bc; }
    }
}

// Pass 2: final reduce over 512 partials
__global__ void __launch_bounds__(R1GRID) k_reduce2() {
    __shared__ float s0[R1GRID], s1[R1GRID];
    __shared__ int   sc[R1GRID];
    const int tid = threadIdx.x;
    s0[tid] = g_part0[tid]; s1[tid] = g_part1[tid]; sc[tid] = g_cntp[tid];
    __syncthreads();
    for (int s = R1GRID / 2; s > 0; s >>= 1) {
        if (tid < s) { s0[tid] += s0[tid + s]; s1[tid] += s1[tid + s]; sc[tid] += sc[tid + s]; }
        __syncthreads();
    }
    if (tid == 0) {
        float n = (float)(sc[0] > 1 ? sc[0] : 1);
        g_mean0 = s0[0] / n;
        g_mean1 = s1[0] / n;
    }
}

// Main kernel: TWO RAYS PER WARP (16 lanes each, 4 steps per lane).
// Scans via width-16 shuffles; sampling phase via warp-private smem (steps + CDF).
__global__ void __launch_bounds__(256) k_main(const float* __restrict__ rd,
                                              const float* __restrict__ cam,
                                              const float* __restrict__ trand,
                                              float* __restrict__ out) {
    __shared__ float s_steps[8][128];   // [warp][half*64 + j]
    __shared__ float s_cdf[8][128];

    const int tid  = threadIdx.x;
    const int wid  = tid >> 5;
    const int lane = tid & 31;
    const int h    = lane & 15;         // lane within ray
    const int half = lane >> 4;         // which ray of the pair
    const int r    = ((blockIdx.x << 3) + wid) * 2 + half;

    const float cx = cam[0], cy = cam[1], cz = cam[2];
    const float cc = cx * cx + cy * cy + cz * cz;

    const float dx = __ldg(rd + 3 * r + 0);
    const float dy = __ldg(rd + 3 * r + 1);
    const float dz = __ldg(rd + 3 * r + 2);
    const float dot = dx * cx + dy * cy + dz * cz;
    const float under = dot * dot - (cc - 1.0f);

    float si0, si1;
    if (under > 0.0f) {
        float sq = sqrtf(under);
        si0 = -sq - dot;
        si1 =  sq - dot;
    } else {
        si0 = g_mean0;
        si1 = g_mean1;
    }
    const float min_d = fmaxf(si0, 0.0f);
    const float max_d = fmaxf(si1, 0.0f);
    const float range = max_d - min_d;
    const float sd = range * (1.0f / 64.0f);

    // b = exp(-inv_s*(sqrt(q)-0.5)) = exp2(K*sqrt(q) + Kh), K = -e^3*log2(e)
    const float K  = -28.977304500f;
    const float Kh =  14.488652250f;

    const float4 t4 = reinterpret_cast<const float4*>(trand)[(size_t)r * 16 + h];
    const float tr[4] = {t4.x, t4.y, t4.z, t4.w};

    float step[4], sig[4], bb[4];
    #pragma unroll
    for (int i = 0; i < 4; i++) {
        int j = 4 * h + i;
        step[i] = fmaf((float)j * (1.0f / 63.0f), range, min_d) + (tr[i] - 0.5f) * sd;
        float q = fmaxf(fmaf(step[i], step[i] + 2.0f * dot, cc), 1e-12f);
        float sq = q * rsqrtf(q);
        bb[i] = exp2f(fmaf(sq, K, Kh));
        sig[i] = __fdividef(1.0f, 1.0f + bb[i]);
    }

    // sig[4h+4] lives on lane h+1 (width-16 shfl keeps halves separate)
    float signext = __shfl_down_sync(FULLM, sig[0], 1, 16);

    float alpha[4];
    #pragma unroll
    for (int i = 0; i < 4; i++) {
        float snext = (i < 3) ? sig[i + 1] : signext;
        float ib = 1.0f + bb[i];
        float invse = ib * (1.0f - 1e-8f * ib);     // ~ 1/(sig+1e-8)
        float a = (sig[i] - snext + 1e-8f) * invse;
        alpha[i] = fminf(fmaxf(a, 0.0f), 1.0f);
    }
    if (h == 15) alpha[3] = 0.0f;                   // slot j=63 is dummy

    // ---- transmittance: product scan over 64 slots (4/lane, width-16) ----
    float g0 = 1.0f - alpha[0] + 1e-7f;
    float g1 = 1.0f - alpha[1] + 1e-7f;
    float g2 = 1.0f - alpha[2] + 1e-7f;
    float g3 = 1.0f - alpha[3] + 1e-7f;
    float m1 = g0, m2 = m1 * g1, m3 = m2 * g2, m4 = m3 * g3;
    float incl = m4;
    #pragma unroll
    for (int off = 1; off < 16; off <<= 1) {
        float v = __shfl_up_sync(FULLM, incl, off, 16);
        if (h >= off) incl *= v;
    }
    float excl = __shfl_up_sync(FULLM, incl, 1, 16);
    if (h == 0) excl = 1.0f;

    float w0 = alpha[0] * excl;
    float w1 = alpha[1] * (excl * m1);
    float w2 = alpha[2] * (excl * m2);
    float w3 = alpha[3] * (excl * m3);

    // ---- unnormalized CDF: sum scan of (w + 1e-8) ----
    float p1 = w0 + 1e-8f;
    float p2 = p1 + (w1 + 1e-8f);
    float p3 = p2 + (w2 + 1e-8f);
    float p4 = p3 + (w3 + 1e-8f);
    float sinc = p4;
    #pragma unroll
    for (int off = 1; off < 16; off <<= 1) {
        float v = __shfl_up_sync(FULLM, sinc, off, 16);
        if (h >= off) sinc += v;
    }
    float sexcl = __shfl_up_sync(FULLM, sinc, 1, 16);
    if (h == 0) sexcl = 0.0f;
    float c0 = sexcl + p1;     // C[4h]
    float c1 = sexcl + p2;
    float c2 = sexcl + p3;
    float c3 = sexcl + p4;

    const float wsum = __shfl_sync(FULLM, c2, 15, 16);   // C[62]
    const float invW = __fdividef(1.0f, wsum);

    // ---- weights out (j = 4h..4h+3, j<63) ----
    {
        float* wout = out + (size_t)P_RAYS * 128 + (size_t)r * 63 + 4 * h;
        wout[0] = w0; wout[1] = w1; wout[2] = w2;
        if (h < 15) wout[3] = w3;
    }

    // ---- stage steps + CDF into warp-private smem ----
    float* ss = &s_steps[wid][half * 64];
    float* sc = &s_cdf[wid][half * 64];
    *reinterpret_cast<float4*>(ss + 4 * h) = make_float4(step[0], step[1], step[2], step[3]);
    *reinterpret_cast<float4*>(sc + 4 * h) = make_float4(c0, c1, c2, c3);
    __syncwarp();

    // ---- importance sampling: lane handles samples 2h, 2h+1 ----
    float z2[2];
    #pragma unroll
    for (int u = 0; u < 2; u++) {
        int k = 2 * h + u;
        float target = (float)(2 * k + 1) * (1.0f / 64.0f) * wsum;
        int p = 0;
        #pragma unroll
        for (int s = 32; s > 0; s >>= 1) {
            int np = p + s;
            if (np <= 63 && sc[np - 1] <= target) p = np;
        }
        if (p > 62) p = 62;
        float cdf_b = (p == 0) ? 0.0f : sc[p - 1];
        float cdf_a = sc[p];
        float bins_b = ss[p];
        float bins_a = ss[p + 1];
        float dN = cdf_a - cdf_b;
        float tt = (target - cdf_b) * ((dN < 1e-8f * wsum) ? invW : __fdividef(1.0f, dN));
        z2[u] = fmaf(tt, bins_a - bins_b, bins_b);
    }

    // ---- z out: float2 per lane ----
    *reinterpret_cast<float2*>(out + (size_t)P_RAYS * 96 + (size_t)r * 32 + 2 * h) =
        make_float2(z2[0], z2[1]);

    // ---- new_samples out: 6 floats per lane as 3x float2 (8B aligned) ----
    {
        float* nsout = out + (size_t)r * 96 + 6 * h;
        *reinterpret_cast<float2*>(nsout + 0) =
            make_float2(fmaf(z2[0], dx, cx), fmaf(z2[0], dy, cy));
        *reinterpret_cast<float2*>(nsout + 2) =
            make_float2(fmaf(z2[0], dz, cz), fmaf(z2[1], dx, cx));
        *reinterpret_cast<float2*>(nsout + 4) =
            make_float2(fmaf(z2[1], dy, cy), fmaf(z2[1], dz, cz));
    }
}

extern "C" void kernel_launch(void* const* d_in, const int* in_sizes, int n_in,
                              void* d_out, int out_size) {
    const float* rd  = (const float*)d_in[0];
    const float* cam = (const float*)d_in[1];
    const float* tr  = (const float*)d_in[2];
    float* out = (float*)d_out;

    k_reduce1<<<R1GRID, 256>>>(rd, cam);
    k_reduce2<<<1, R1GRID>>>();
    k_main<<<P_RAYS / 16, 256>>>(rd, cam, tr, out);
}